// round 1
// baseline (speedup 1.0000x reference)
#include <cuda_runtime.h>
#include <cstdint>
#include <cstddef>

// Shapes (fixed by the problem)
//   input1: (8, 256, 512) f32
//   input2: (8, 256, 512) f32
//   w1:     (512, 128, 512) f32   -> viewed as (512 x 65536) row-major
//   w2:     (1025, 128) f32       -> w2a = rows [0,512), w2b = rows [512,1024), bias = row 1024
//   out:    (8, 256, 256, 128) f32
//
// Stage 1: U[b, x*128+o, j] = sum_i in1[b,x,i] * w1[i, o*512+j]      (per-b GEMM 256 x 65536 x 512)
// Stage 2: out[b,x,y,o]     = sum_j U[b, x*128+o, j] * in2[b,y,j]
//                             + p[b,x,o] + q[b,y,o] + bias[o]        (per-b GEMM 32768 x 256 x 512)

#define B_ 8
#define L_ 256
#define D_ 512
#define O_ 128
#define N1 (O_ * D_)   // 65536

// 537 MB scratch for U, 2x 1 MB for p/q. Device globals (no runtime alloc).
__device__ float g_U[(size_t)B_ * L_ * N1];
__device__ float g_p[B_ * L_ * O_];
__device__ float g_q[B_ * L_ * O_];

// ---------------------------------------------------------------------------
// p/q kernel: p[b,l,o] = sum_i in1[b,l,i]*w2[i,o]; q likewise with in2, w2b.
// grid: (L/16, B, 2), block: 128 threads (one o per thread).
// ---------------------------------------------------------------------------
__global__ __launch_bounds__(128) void pq_kernel(const float* __restrict__ in1,
                                                 const float* __restrict__ in2,
                                                 const float* __restrict__ w2) {
    const int o  = threadIdx.x;
    const int lt = blockIdx.x * 16;
    const int b  = blockIdx.y;
    const int which = blockIdx.z;

    const float* inp = (which ? in2 : in1) + ((size_t)b * L_ + lt) * D_;
    const float* w   = w2 + (size_t)which * D_ * O_;

    __shared__ float sin_[16][D_];
    for (int idx = threadIdx.x; idx < 16 * D_; idx += 128)
        sin_[idx / D_][idx % D_] = inp[idx];
    __syncthreads();

    float acc[16];
#pragma unroll
    for (int l = 0; l < 16; l++) acc[l] = 0.f;

    for (int i = 0; i < D_; i++) {
        const float wv = w[(size_t)i * O_ + o];
#pragma unroll
        for (int l = 0; l < 16; l++) acc[l] = fmaf(sin_[l][i], wv, acc[l]);
    }

    float* dst = (which ? g_q : g_p) + ((size_t)b * L_ + lt) * O_;
#pragma unroll
    for (int l = 0; l < 16; l++) dst[(size_t)l * O_ + o] = acc[l];
}

// ---------------------------------------------------------------------------
// Stage 1: per-b GEMM  C(256 x 65536) = A(256 x 512) @ W(512 x 65536)
// 128x128 tile, K-tile 16, 256 threads, 8x8 register blocking.
// grid: (N1/128 = 512, 256/128 = 2, B)
// ---------------------------------------------------------------------------
__global__ __launch_bounds__(256) void stage1_kernel(const float* __restrict__ A,
                                                     const float* __restrict__ W) {
    const int b  = blockIdx.z;
    const int n0 = blockIdx.x * 128;
    const int m0 = blockIdx.y * 128;

    const float* Ab = A + (size_t)b * L_ * D_;
    float*       Ub = g_U + (size_t)b * L_ * N1;

    __shared__ float As[16][128];
    __shared__ float Bs[16][128];

    const int tx = threadIdx.x & 15;
    const int ty = threadIdx.x >> 4;
    const int rm = ty * 8;
    const int rn = tx * 8;

    float acc[8][8];
#pragma unroll
    for (int i = 0; i < 8; i++)
#pragma unroll
        for (int j = 0; j < 8; j++) acc[i][j] = 0.f;

    const int ar = threadIdx.x >> 2;          // 0..63
    const int ac = (threadIdx.x & 3) * 4;     // 0,4,8,12
    const int bk = threadIdx.x >> 5;          // 0..7
    const int bc = (threadIdx.x & 31) * 4;    // 0..124

    for (int k0 = 0; k0 < D_; k0 += 16) {
        // A tile: 128 rows (m) x 16 cols (k), stored transposed As[k][m]
#pragma unroll
        for (int rr = 0; rr < 128; rr += 64) {
            float4 v = *(const float4*)&Ab[(size_t)(m0 + ar + rr) * D_ + k0 + ac];
            As[ac + 0][ar + rr] = v.x;
            As[ac + 1][ar + rr] = v.y;
            As[ac + 2][ar + rr] = v.z;
            As[ac + 3][ar + rr] = v.w;
        }
        // W tile: 16 rows (k) x 128 cols (n), direct Bs[k][n]
#pragma unroll
        for (int kk = 0; kk < 16; kk += 8) {
            float4 v = *(const float4*)&W[(size_t)(k0 + bk + kk) * N1 + n0 + bc];
            *(float4*)&Bs[bk + kk][bc] = v;
        }
        __syncthreads();

#pragma unroll
        for (int k = 0; k < 16; k++) {
            float a_[8], b_[8];
#pragma unroll
            for (int i = 0; i < 8; i++) a_[i] = As[k][rm + i];
#pragma unroll
            for (int j = 0; j < 8; j++) b_[j] = Bs[k][rn + j];
#pragma unroll
            for (int i = 0; i < 8; i++)
#pragma unroll
                for (int j = 0; j < 8; j++) acc[i][j] = fmaf(a_[i], b_[j], acc[i][j]);
        }
        __syncthreads();
    }

#pragma unroll
    for (int i = 0; i < 8; i++) {
        float* dst = &Ub[(size_t)(m0 + rm + i) * N1 + n0 + rn];
        *(float4*)&dst[0] = make_float4(acc[i][0], acc[i][1], acc[i][2], acc[i][3]);
        *(float4*)&dst[4] = make_float4(acc[i][4], acc[i][5], acc[i][6], acc[i][7]);
    }
}

// ---------------------------------------------------------------------------
// Stage 2: per-b GEMM  C(32768 x 256) = U(32768 x 512) @ in2(256 x 512)^T
// with fused epilogue: + p[b,x,o] + q[b,y,o] + bias[o], scattered to out.
// M-tile rows are exactly (x = blockIdx.y, o = row-in-tile).
// grid: (256/128 = 2, 32768/128 = 256, B)
// ---------------------------------------------------------------------------
__global__ __launch_bounds__(256) void stage2_kernel(const float* __restrict__ in2,
                                                     const float* __restrict__ w2,
                                                     float* __restrict__ out) {
    const int b  = blockIdx.z;
    const int n0 = blockIdx.x * 128;   // y tile
    const int x  = blockIdx.y;         // m0 = x*128
    const int m0 = x * 128;

    const float* Ab = g_U + (size_t)b * L_ * N1;        // (32768 x 512)
    const float* Bb = in2 + (size_t)b * L_ * D_;        // (256 x 512), rows = y

    __shared__ float As[16][128];
    __shared__ float Bs[16][128];

    const int tx = threadIdx.x & 15;
    const int ty = threadIdx.x >> 4;
    const int rm = ty * 8;   // o base
    const int rn = tx * 8;   // y-in-tile base

    float acc[8][8];
#pragma unroll
    for (int i = 0; i < 8; i++)
#pragma unroll
        for (int j = 0; j < 8; j++) acc[i][j] = 0.f;

    const int ar = threadIdx.x >> 2;
    const int ac = (threadIdx.x & 3) * 4;

    for (int k0 = 0; k0 < D_; k0 += 16) {
        // A tile (U): 128 rows x 16 k, transposed
#pragma unroll
        for (int rr = 0; rr < 128; rr += 64) {
            float4 v = *(const float4*)&Ab[(size_t)(m0 + ar + rr) * D_ + k0 + ac];
            As[ac + 0][ar + rr] = v.x;
            As[ac + 1][ar + rr] = v.y;
            As[ac + 2][ar + rr] = v.z;
            As[ac + 3][ar + rr] = v.w;
        }
        // B tile (in2 rows = y): 128 rows x 16 k, transposed
#pragma unroll
        for (int rr = 0; rr < 128; rr += 64) {
            float4 v = *(const float4*)&Bb[(size_t)(n0 + ar + rr) * D_ + k0 + ac];
            Bs[ac + 0][ar + rr] = v.x;
            Bs[ac + 1][ar + rr] = v.y;
            Bs[ac + 2][ar + rr] = v.z;
            Bs[ac + 3][ar + rr] = v.w;
        }
        __syncthreads();

#pragma unroll
        for (int k = 0; k < 16; k++) {
            float a_[8], b_[8];
#pragma unroll
            for (int i = 0; i < 8; i++) a_[i] = As[k][rm + i];
#pragma unroll
            for (int j = 0; j < 8; j++) b_[j] = Bs[k][rn + j];
#pragma unroll
            for (int i = 0; i < 8; i++)
#pragma unroll
                for (int j = 0; j < 8; j++) acc[i][j] = fmaf(a_[i], b_[j], acc[i][j]);
        }
        __syncthreads();
    }

    // Epilogue: out[b,x,y,o] = acc + p[b,x,o] + q[b,y,o] + bias[o]
    const float* pb   = g_p + ((size_t)b * L_ + x) * O_;     // [o]
    const float* qb   = g_q + (size_t)b * L_ * O_;           // [y*128 + o]
    const float* bias = w2 + (size_t)1024 * O_;              // [o]
    float* outb = out + ((size_t)b * L_ + x) * L_ * O_;      // + y*128 + o

    float po[8];
#pragma unroll
    for (int i = 0; i < 8; i++) po[i] = pb[rm + i] + bias[rm + i];

#pragma unroll
    for (int j = 0; j < 8; j++) {
        const int y = n0 + rn + j;
        const float* qrow = &qb[(size_t)y * O_ + rm];
        float4 q0 = *(const float4*)&qrow[0];
        float4 q1 = *(const float4*)&qrow[4];
        float4 v0 = make_float4(acc[0][j] + po[0] + q0.x,
                                acc[1][j] + po[1] + q0.y,
                                acc[2][j] + po[2] + q0.z,
                                acc[3][j] + po[3] + q0.w);
        float4 v1 = make_float4(acc[4][j] + po[4] + q1.x,
                                acc[5][j] + po[5] + q1.y,
                                acc[6][j] + po[6] + q1.z,
                                acc[7][j] + po[7] + q1.w);
        float* dst = outb + (size_t)y * O_ + rm;
        *(float4*)&dst[0] = v0;
        *(float4*)&dst[4] = v1;
    }
}

extern "C" void kernel_launch(void* const* d_in, const int* in_sizes, int n_in,
                              void* d_out, int out_size) {
    const float* in1 = (const float*)d_in[0];
    const float* in2 = (const float*)d_in[1];
    const float* w1  = (const float*)d_in[2];
    const float* w2  = (const float*)d_in[3];
    float* out = (float*)d_out;

    pq_kernel<<<dim3(L_ / 16, B_, 2), 128>>>(in1, in2, w2);
    stage1_kernel<<<dim3(N1 / 128, L_ / 128, B_), 256>>>(in1, w1);
    stage2_kernel<<<dim3(L_ / 128, (L_ * O_) / 128, B_), 256>>>(in2, w2, out);
}

// round 3
// speedup vs baseline: 2.0509x; 2.0509x over previous
#include <cuda_runtime.h>
#include <cuda_bf16.h>
#include <cstdint>
#include <cstddef>

// Biaffine: out[b,x,y,o] = sum_ij in1[b,x,i] w1[i,o,j] in2[b,y,j]
//                        + p[b,x,o] + q[b,y,o] + bias[o]
// Split-bf16 3-GEMM as one K=1536 GEMM: A segs {hi,lo,hi}, B segs {hi,hi,lo}.
// Stage1: U[(b,x)*128+o][j] = in1[b,x,:] @ w1t   C(2048 x 65536), K->1536
// Stage2: out: C(128 x 256 per (b,x)) = U @ in2^T, epilogue adds p,q,bias.
// Tensor path: mma.sync.aligned.m16n8k16 bf16 (plain sm_103-compatible PTX).

#define B_ 8
#define L_ 256
#define D_ 512
#define O_ 128
#define NCH 48                  // 1536 / 32
#define ABUF 10240              // 128 rows * 80B
#define SMEM_BYTES 61440        // 3 * (ABUF + BBUF)

using bf = __nv_bfloat16;

// -------------------- device globals (no runtime alloc) --------------------
__device__ __align__(128) bf g_Ahi[2048 * 512];
__device__ __align__(128) bf g_Alo[2048 * 512];
__device__ __align__(128) bf g_I2hi[2048 * 512];
__device__ __align__(128) bf g_I2lo[2048 * 512];
__device__ __align__(128) bf g_Whi[(size_t)65536 * 512];
__device__ __align__(128) bf g_Wlo[(size_t)65536 * 512];
__device__ __align__(128) bf g_Uhi[(size_t)262144 * 512];
__device__ __align__(128) bf g_Ulo[(size_t)262144 * 512];
__device__ __align__(128) float g_p[2048 * 128];
__device__ __align__(128) float g_q[2048 * 128];

// -------------------- helpers --------------------
__device__ __forceinline__ uint32_t smem_u32(const void* p) {
    uint32_t a;
    asm("{ .reg .u64 t; cvta.to.shared.u64 t, %1; cvt.u32.u64 %0, t; }" : "=r"(a) : "l"(p));
    return a;
}
__device__ __forceinline__ void cpa16(uint32_t s, const void* g) {
    asm volatile("cp.async.cg.shared.global [%0], [%1], 16;" :: "r"(s), "l"(g));
}
#define CP_COMMIT asm volatile("cp.async.commit_group;" ::: "memory")
#define CP_WAIT1  asm volatile("cp.async.wait_group 1;" ::: "memory")
#define CP_WAIT0  asm volatile("cp.async.wait_group 0;" ::: "memory")

__device__ __forceinline__ void ldmx4(uint32_t* r, uint32_t addr) {
    asm volatile("ldmatrix.sync.aligned.m8n8.x4.shared.b16 {%0,%1,%2,%3}, [%4];"
                 : "=r"(r[0]), "=r"(r[1]), "=r"(r[2]), "=r"(r[3]) : "r"(addr));
}
__device__ __forceinline__ void mma16816(float* c, const uint32_t* a, uint32_t b0, uint32_t b1) {
    asm("mma.sync.aligned.m16n8k16.row.col.f32.bf16.bf16.f32 "
        "{%0,%1,%2,%3},{%4,%5,%6,%7},{%8,%9},{%0,%1,%2,%3};"
        : "+f"(c[0]), "+f"(c[1]), "+f"(c[2]), "+f"(c[3])
        : "r"(a[0]), "r"(a[1]), "r"(a[2]), "r"(a[3]), "r"(b0), "r"(b1));
}
__device__ __forceinline__ uint32_t pack_bf2(float lo, float hi) {
    __nv_bfloat162 h = __floats2bfloat162_rn(lo, hi);
    return *(uint32_t*)&h;
}

// -------------------- chunk loader (A/B tiles 128x32 bf16, stride 80B) -----
__device__ __forceinline__ void load_chunk(char* smem, int buf,
                                           const bf* __restrict__ a,
                                           const bf* __restrict__ b,
                                           size_t a_row0, size_t b_row0,
                                           int kcol, int t) {
    const int r = t >> 2, c = t & 3;
    const uint32_t sa = smem_u32(smem) + buf * ABUF;
    const uint32_t sb = sa + 3 * ABUF;
    const bf* ga = a + (a_row0 + r) * 512 + kcol + c * 8;
    const bf* gb = b + (b_row0 + r) * 512 + kcol + c * 8;
    cpa16(sa + r * 80 + c * 16, ga);
    cpa16(sa + (r + 64) * 80 + c * 16, ga + (size_t)64 * 512);
    cpa16(sb + r * 80 + c * 16, gb);
    cpa16(sb + (r + 64) * 80 + c * 16, gb + (size_t)64 * 512);
}

// -------------------- shared mainloop --------------------
// acc[mt][nt][4]: warp tile 64(M) x 32(N): mt 0..3 (m16), nt 0..3 (n8)
__device__ __forceinline__ void mma_mainloop(char* smem,
                                             const bf* a_hi, const bf* a_lo,
                                             const bf* b_hi, const bf* b_lo,
                                             size_t a_row0, size_t b_row0,
                                             float acc[4][4][4],
                                             int wm, int wn, int lane, int t) {
    const bf* aseg[3] = {a_hi, a_lo, a_hi};
    const bf* bseg[3] = {b_hi, b_hi, b_lo};

    const uint32_t sbase = smem_u32(smem);
    const uint32_t lro = (lane & 15) * 80 + (lane >> 4) * 16;   // ldmatrix lane offset

    load_chunk(smem, 0, aseg[0], bseg[0], a_row0, b_row0, 0, t);  CP_COMMIT;
    load_chunk(smem, 1, aseg[0], bseg[0], a_row0, b_row0, 32, t); CP_COMMIT;

    for (int cch = 0; cch < NCH; cch++) {
        const int buf = cch % 3;
        if (cch < NCH - 1) { CP_WAIT1; } else { CP_WAIT0; }
        __syncthreads();

        const uint32_t abase = sbase + buf * ABUF + (wm * 64) * 80 + lro;
        const uint32_t bbase = sbase + 3 * ABUF + buf * ABUF + (wn * 32) * 80 + lro;
#pragma unroll
        for (int kst = 0; kst < 2; kst++) {
            uint32_t areg[4][4], breg[2][4];
#pragma unroll
            for (int mt = 0; mt < 4; mt++)
                ldmx4(areg[mt], abase + mt * (16 * 80) + kst * 32);
#pragma unroll
            for (int n2 = 0; n2 < 2; n2++)
                ldmx4(breg[n2], bbase + n2 * (16 * 80) + kst * 32);
#pragma unroll
            for (int mt = 0; mt < 4; mt++)
#pragma unroll
                for (int n2 = 0; n2 < 2; n2++) {
                    mma16816(acc[mt][n2 * 2 + 0], areg[mt], breg[n2][0], breg[n2][2]);
                    mma16816(acc[mt][n2 * 2 + 1], areg[mt], breg[n2][1], breg[n2][3]);
                }
        }

        if (cch + 2 < NCH) {
            const int nc = cch + 2;
            const int seg = nc >> 4;
            load_chunk(smem, nc % 3, aseg[seg], bseg[seg], a_row0, b_row0,
                       (nc & 15) * 32, t);
            CP_COMMIT;
        }
    }
}

// -------------------- stage 1 --------------------
// grid (16, 512): x = m-tile (2048/128), y = n-tile (65536/128)
__global__ __launch_bounds__(256, 2) void stage1_mma() {
    extern __shared__ char smem[];
    const int t = threadIdx.x, lane = t & 31, wid = t >> 5;
    const int wm = wid & 1, wn = wid >> 1;
    const int g = lane >> 2, qp = lane & 3;

    const size_t m0 = (size_t)blockIdx.x * 128;
    const int n0 = blockIdx.y * 128;
    const int o = n0 >> 9, j0 = n0 & 511;

    float acc[4][4][4];
#pragma unroll
    for (int i = 0; i < 4; i++)
#pragma unroll
        for (int j = 0; j < 4; j++)
#pragma unroll
            for (int k = 0; k < 4; k++) acc[i][j][k] = 0.f;

    mma_mainloop(smem, g_Ahi, g_Alo, g_Whi, g_Wlo, m0, (size_t)n0, acc, wm, wn, lane, t);

    // epilogue: re-split C -> (Uhi, Ulo) via smem staging, coalesced 16B stores
    for (int ph = 0; ph < 2; ph++) {
        __syncthreads();
        if (wm == ph) {
#pragma unroll
            for (int mt = 0; mt < 4; mt++) {
                const int lr = mt * 16 + g;
#pragma unroll
                for (int nt = 0; nt < 4; nt++) {
                    const int colb = (wn * 32 + nt * 8 + qp * 2) * 2;
                    float v0 = acc[mt][nt][0], v1 = acc[mt][nt][1];
                    float v2 = acc[mt][nt][2], v3 = acc[mt][nt][3];
                    float h0 = __bfloat162float(__float2bfloat16(v0));
                    float h1 = __bfloat162float(__float2bfloat16(v1));
                    float h2 = __bfloat162float(__float2bfloat16(v2));
                    float h3 = __bfloat162float(__float2bfloat16(v3));
                    *(uint32_t*)(smem + lr * 272 + colb)               = pack_bf2(v0, v1);
                    *(uint32_t*)(smem + 17408 + lr * 272 + colb)       = pack_bf2(v0 - h0, v1 - h1);
                    *(uint32_t*)(smem + (lr + 8) * 272 + colb)         = pack_bf2(v2, v3);
                    *(uint32_t*)(smem + 17408 + (lr + 8) * 272 + colb) = pack_bf2(v2 - h2, v3 - h3);
                }
            }
        }
        __syncthreads();
#pragma unroll
        for (int i = 0; i < 8; i++) {
            const int task = t + i * 256;
            const int p = task >> 10, rem = task & 1023;
            const int r = rem >> 4, cch = rem & 15;
            uint4 v = *(uint4*)(smem + p * 17408 + r * 272 + cch * 16);
            const size_t m = m0 + ph * 64 + r;
            bf* dst = (p ? g_Ulo : g_Uhi) + (m * 128 + o) * 512 + j0 + cch * 8;
            *(uint4*)dst = v;
        }
    }
}

// -------------------- stage 2 --------------------
// grid (2, 256, 8): x = y-tile, y = x index, z = b
__global__ __launch_bounds__(256, 2) void stage2_mma(const float* __restrict__ w2,
                                                     float* __restrict__ out) {
    extern __shared__ char smem[];
    __shared__ float pb_s[128];
    const int t = threadIdx.x, lane = t & 31, wid = t >> 5;
    const int wm = wid & 1, wn = wid >> 1;
    const int g = lane >> 2, qp = lane & 3;

    const int b = blockIdx.z, x = blockIdx.y, n0 = blockIdx.x * 128;
    const size_t a_row0 = ((size_t)b * L_ + x) * 128;   // rows = o
    const size_t b_row0 = (size_t)b * L_ + n0;          // rows = y

    float acc[4][4][4];
#pragma unroll
    for (int i = 0; i < 4; i++)
#pragma unroll
        for (int j = 0; j < 4; j++)
#pragma unroll
            for (int k = 0; k < 4; k++) acc[i][j][k] = 0.f;

    mma_mainloop(smem, g_Uhi, g_Ulo, g_I2hi, g_I2lo, a_row0, b_row0, acc, wm, wn, lane, t);

    __syncthreads();
    if (t < 128) pb_s[t] = g_p[((size_t)b * L_ + x) * 128 + t] + w2[(size_t)1024 * 128 + t];

    float* S = (float*)smem;   // [o-local 64][129] f32
    for (int ph = 0; ph < 2; ph++) {
        __syncthreads();
        if (wm == ph) {
#pragma unroll
            for (int mt = 0; mt < 4; mt++) {
                const int lr = mt * 16 + g;
                const float pb0 = pb_s[ph * 64 + lr];
                const float pb1 = pb_s[ph * 64 + lr + 8];
#pragma unroll
                for (int nt = 0; nt < 4; nt++) {
                    const int col = wn * 32 + nt * 8 + qp * 2;
                    S[lr * 129 + col]           = acc[mt][nt][0] + pb0;
                    S[lr * 129 + col + 1]       = acc[mt][nt][1] + pb0;
                    S[(lr + 8) * 129 + col]     = acc[mt][nt][2] + pb1;
                    S[(lr + 8) * 129 + col + 1] = acc[mt][nt][3] + pb1;
                }
            }
        }
        __syncthreads();
#pragma unroll
        for (int i = 0; i < 8; i++) {
            const int task = t + i * 256;
            const int y = task >> 4, oc = task & 15;
            const int yg = n0 + y;
            const int o0 = ph * 64 + oc * 4;
            float4 qv = *(const float4*)(g_q + ((size_t)b * L_ + yg) * 128 + o0);
            float4 v;
            v.x = S[(oc * 4 + 0) * 129 + y] + qv.x;
            v.y = S[(oc * 4 + 1) * 129 + y] + qv.y;
            v.z = S[(oc * 4 + 2) * 129 + y] + qv.z;
            v.w = S[(oc * 4 + 3) * 129 + y] + qv.w;
            *(float4*)(out + (((size_t)b * L_ + x) * L_ + yg) * 128 + o0) = v;
        }
    }
}

// -------------------- conversion kernels --------------------
__global__ __launch_bounds__(256) void split_kernel(const float* __restrict__ src, int which) {
    const int i = blockIdx.x * 256 + threadIdx.x;
    float v = src[i];
    bf h = __float2bfloat16(v);
    bf l = __float2bfloat16(v - __bfloat162float(h));
    if (which) { g_I2hi[i] = h; g_I2lo[i] = l; }
    else       { g_Ahi[i]  = h; g_Alo[i]  = l; }
}

__global__ __launch_bounds__(256) void w1t_kernel(const float* __restrict__ w1) {
    __shared__ float sm[32][33];
    const int n0 = blockIdx.x * 32;
    const int k0 = blockIdx.y * 32;
    const int tx = threadIdx.x, ty = threadIdx.y;
    for (int i = ty; i < 32; i += 8)
        sm[i][tx] = w1[(size_t)(k0 + i) * 65536 + n0 + tx];
    __syncthreads();
    for (int i = ty; i < 32; i += 8) {
        float v = sm[tx][i];
        bf h = __float2bfloat16(v);
        bf l = __float2bfloat16(v - __bfloat162float(h));
        g_Whi[(size_t)(n0 + i) * 512 + k0 + tx] = h;
        g_Wlo[(size_t)(n0 + i) * 512 + k0 + tx] = l;
    }
}

__global__ __launch_bounds__(128) void pq_kernel(const float* __restrict__ in1,
                                                 const float* __restrict__ in2,
                                                 const float* __restrict__ w2) {
    const int o = threadIdx.x;
    const int lt = blockIdx.x * 16;
    const int b = blockIdx.y;
    const int which = blockIdx.z;

    const float* inp = (which ? in2 : in1) + ((size_t)b * L_ + lt) * D_;
    const float* w = w2 + (size_t)which * D_ * O_;

    __shared__ float sin_[16][D_];
    for (int idx = threadIdx.x; idx < 16 * D_; idx += 128)
        sin_[idx / D_][idx % D_] = inp[idx];
    __syncthreads();

    float acc[16];
#pragma unroll
    for (int l = 0; l < 16; l++) acc[l] = 0.f;
    for (int i = 0; i < D_; i++) {
        const float wv = w[(size_t)i * O_ + o];
#pragma unroll
        for (int l = 0; l < 16; l++) acc[l] = fmaf(sin_[l][i], wv, acc[l]);
    }
    float* dst = (which ? g_q : g_p) + ((size_t)b * L_ + lt) * O_;
#pragma unroll
    for (int l = 0; l < 16; l++) dst[(size_t)l * O_ + o] = acc[l];
}

// -------------------- host --------------------
extern "C" void kernel_launch(void* const* d_in, const int* in_sizes, int n_in,
                              void* d_out, int out_size) {
    const float* in1 = (const float*)d_in[0];
    const float* in2 = (const float*)d_in[1];
    const float* w1  = (const float*)d_in[2];
    const float* w2  = (const float*)d_in[3];
    float* out = (float*)d_out;

    cudaFuncSetAttribute(stage1_mma, cudaFuncAttributeMaxDynamicSharedMemorySize, SMEM_BYTES);
    cudaFuncSetAttribute(stage2_mma, cudaFuncAttributeMaxDynamicSharedMemorySize, SMEM_BYTES);

    split_kernel<<<2048 * 512 / 256, 256>>>(in1, 0);
    split_kernel<<<2048 * 512 / 256, 256>>>(in2, 1);
    w1t_kernel<<<dim3(65536 / 32, 512 / 32), dim3(32, 8)>>>(w1);
    pq_kernel<<<dim3(L_ / 16, B_, 2), 128>>>(in1, in2, w2);

    stage1_mma<<<dim3(16, 512), 256, SMEM_BYTES>>>();
    stage2_mma<<<dim3(2, 256, 8), 256, SMEM_BYTES>>>(w2, out);
}

// round 4
// speedup vs baseline: 3.2068x; 1.5636x over previous
#include <cuda_runtime.h>
#include <cuda_fp16.h>
#include <cstdint>
#include <cstddef>

// Biaffine: out[b,x,y,o] = sum_ij in1[b,x,i] w1[i,o,j] in2[b,y,j] + p + q + bias
// fp16 2-term split scheme:
//   stage1: U = (in1_hi + in1_lo) @ w1_hi          (dual-A, K=512)
//   stage2: out = U_hi @ (in2_hi + in2_lo)^T       (dual-B, K=512)
// Dropped terms ~2^-12 RMS each -> total ~4e-4 rel err (< 1e-3 threshold).
// Tensor path: mma.sync.aligned.m16n8k16.f32.f16.f16.f32 (plain sm_103 PTX).

#define B_ 8
#define L_ 256
#define D_ 512
#define O_ 128
#define NCH 16                  // 512 / 32
#define TBUF 10240              // 128 rows * 80B
#define CBUF (3 * TBUF)         // 3 tiles per chunk buffer
#define SMEM_BYTES 92160        // 3 * CBUF

using hf = __half;

// -------------------- device globals (no runtime alloc) --------------------
__device__ __align__(128) hf g_Ahi[2048 * 512];
__device__ __align__(128) hf g_Alo[2048 * 512];
__device__ __align__(128) hf g_I2hi[2048 * 512];
__device__ __align__(128) hf g_I2lo[2048 * 512];
__device__ __align__(128) hf g_Whi[(size_t)65536 * 512];
__device__ __align__(128) hf g_Uhi[(size_t)262144 * 512];
__device__ __align__(128) float g_p[2048 * 128];
__device__ __align__(128) float g_q[2048 * 128];

// -------------------- helpers --------------------
__device__ __forceinline__ uint32_t smem_u32(const void* p) {
    uint32_t a;
    asm("{ .reg .u64 t; cvta.to.shared.u64 t, %1; cvt.u32.u64 %0, t; }" : "=r"(a) : "l"(p));
    return a;
}
__device__ __forceinline__ void cpa16(uint32_t s, const void* g) {
    asm volatile("cp.async.cg.shared.global [%0], [%1], 16;" :: "r"(s), "l"(g));
}
#define CP_COMMIT asm volatile("cp.async.commit_group;" ::: "memory")
#define CP_WAIT1  asm volatile("cp.async.wait_group 1;" ::: "memory")
#define CP_WAIT0  asm volatile("cp.async.wait_group 0;" ::: "memory")

__device__ __forceinline__ void ldmx4(uint32_t* r, uint32_t addr) {
    asm volatile("ldmatrix.sync.aligned.m8n8.x4.shared.b16 {%0,%1,%2,%3}, [%4];"
                 : "=r"(r[0]), "=r"(r[1]), "=r"(r[2]), "=r"(r[3]) : "r"(addr));
}
__device__ __forceinline__ void mma16816(float* c, const uint32_t* a, uint32_t b0, uint32_t b1) {
    asm("mma.sync.aligned.m16n8k16.row.col.f32.f16.f16.f32 "
        "{%0,%1,%2,%3},{%4,%5,%6,%7},{%8,%9},{%0,%1,%2,%3};"
        : "+f"(c[0]), "+f"(c[1]), "+f"(c[2]), "+f"(c[3])
        : "r"(a[0]), "r"(a[1]), "r"(a[2]), "r"(a[3]), "r"(b0), "r"(b1));
}

// -------------------- chunk loader: 3 tiles of 128x32 fp16 --------------------
__device__ __forceinline__ void load3(uint32_t sbase, int buf,
                                      const hf* __restrict__ t0,
                                      const hf* __restrict__ t1,
                                      const hf* __restrict__ t2,
                                      int kcol, int t) {
    const int r = t >> 2, c = t & 3;
    const uint32_t so = sbase + buf * CBUF + r * 80 + c * 16;
    const size_t go = (size_t)r * 512 + kcol + c * 8;
    const hf* gp[3] = {t0 + go, t1 + go, t2 + go};
#pragma unroll
    for (int s = 0; s < 3; s++)
#pragma unroll
        for (int p = 0; p < 4; p++)
            cpa16(so + s * TBUF + p * (32 * 80), gp[s] + (size_t)32 * p * 512);
}

// -------------------- shared mainloop --------------------
// CTA tile 128x128, 4 warps in 2x2, warp tile 64x64.
// acc[mt][nt][4]: mt 0..3 (m16), nt 0..7 (n8).
// DUAL_A: slots {A_hi, A_lo, B};  !DUAL_A: slots {A, B_hi, B_lo}.
template <bool DUAL_A>
__device__ __forceinline__ void mma_mainloop(char* smem,
                                             const hf* p0, const hf* p1, const hf* p2,
                                             float acc[4][8][4],
                                             int wm, int wn, int lane, int t) {
    const uint32_t sbase = smem_u32(smem);
    const uint32_t lro = (lane & 15) * 80 + (lane >> 4) * 16;

    load3(sbase, 0, p0, p1, p2, 0, t);  CP_COMMIT;
    load3(sbase, 1, p0, p1, p2, 32, t); CP_COMMIT;

    for (int cch = 0; cch < NCH; cch++) {
        const int buf = cch % 3;
        if (cch < NCH - 1) { CP_WAIT1; } else { CP_WAIT0; }
        __syncthreads();

        const uint32_t bb = sbase + buf * CBUF;
        const uint32_t aoff = wm * (64 * 80) + lro;
        const uint32_t boff = wn * (64 * 80) + lro;
        // slot bases
        const uint32_t sA0 = DUAL_A ? (bb + aoff)            : (bb + aoff);
        const uint32_t sA1 = DUAL_A ? (bb + TBUF + aoff)     : 0;
        const uint32_t sB0 = DUAL_A ? (bb + 2 * TBUF + boff) : (bb + TBUF + boff);
        const uint32_t sB1 = DUAL_A ? 0                      : (bb + 2 * TBUF + boff);

#pragma unroll
        for (int kst = 0; kst < 2; kst++) {
            const uint32_t ko = kst * 32;
            uint32_t ar[4][4], br[4][4];
            if (DUAL_A) {
#pragma unroll
                for (int n2 = 0; n2 < 4; n2++) ldmx4(br[n2], sB0 + n2 * (16 * 80) + ko);
#pragma unroll
                for (int mt = 0; mt < 4; mt++) ldmx4(ar[mt], sA0 + mt * (16 * 80) + ko);
#pragma unroll
                for (int mt = 0; mt < 4; mt++)
#pragma unroll
                    for (int n2 = 0; n2 < 4; n2++) {
                        mma16816(acc[mt][n2 * 2 + 0], ar[mt], br[n2][0], br[n2][2]);
                        mma16816(acc[mt][n2 * 2 + 1], ar[mt], br[n2][1], br[n2][3]);
                    }
#pragma unroll
                for (int mt = 0; mt < 4; mt++) ldmx4(ar[mt], sA1 + mt * (16 * 80) + ko);
#pragma unroll
                for (int mt = 0; mt < 4; mt++)
#pragma unroll
                    for (int n2 = 0; n2 < 4; n2++) {
                        mma16816(acc[mt][n2 * 2 + 0], ar[mt], br[n2][0], br[n2][2]);
                        mma16816(acc[mt][n2 * 2 + 1], ar[mt], br[n2][1], br[n2][3]);
                    }
            } else {
#pragma unroll
                for (int mt = 0; mt < 4; mt++) ldmx4(ar[mt], sA0 + mt * (16 * 80) + ko);
#pragma unroll
                for (int n2 = 0; n2 < 4; n2++) ldmx4(br[n2], sB0 + n2 * (16 * 80) + ko);
#pragma unroll
                for (int mt = 0; mt < 4; mt++)
#pragma unroll
                    for (int n2 = 0; n2 < 4; n2++) {
                        mma16816(acc[mt][n2 * 2 + 0], ar[mt], br[n2][0], br[n2][2]);
                        mma16816(acc[mt][n2 * 2 + 1], ar[mt], br[n2][1], br[n2][3]);
                    }
#pragma unroll
                for (int n2 = 0; n2 < 4; n2++) ldmx4(br[n2], sB1 + n2 * (16 * 80) + ko);
#pragma unroll
                for (int mt = 0; mt < 4; mt++)
#pragma unroll
                    for (int n2 = 0; n2 < 4; n2++) {
                        mma16816(acc[mt][n2 * 2 + 0], ar[mt], br[n2][0], br[n2][2]);
                        mma16816(acc[mt][n2 * 2 + 1], ar[mt], br[n2][1], br[n2][3]);
                    }
            }
        }

        if (cch + 2 < NCH)
            { load3(sbase, (cch + 2) % 3, p0, p1, p2, (cch + 2) * 32, t); CP_COMMIT; }
    }
}

// -------------------- stage 1: U = (in1_hi + in1_lo) @ Whi --------------------
// grid (16, 512): x = m-tile (2048/128), y = n-tile (65536/128)
__global__ __launch_bounds__(128, 2) void stage1_mma() {
    extern __shared__ char smem[];
    const int t = threadIdx.x, lane = t & 31, wid = t >> 5;
    const int wm = wid & 1, wn = wid >> 1;
    const int g = lane >> 2, qp = lane & 3;

    const size_t m0 = (size_t)blockIdx.x * 128;
    const int n0 = blockIdx.y * 128;
    const int o = n0 >> 9, j0 = n0 & 511;

    float acc[4][8][4];
#pragma unroll
    for (int i = 0; i < 4; i++)
#pragma unroll
        for (int j = 0; j < 8; j++)
#pragma unroll
            for (int k = 0; k < 4; k++) acc[i][j][k] = 0.f;

    mma_mainloop<true>(smem, g_Ahi + m0 * 512, g_Alo + m0 * 512,
                       g_Whi + (size_t)n0 * 512, acc, wm, wn, lane, t);

    // epilogue: fp32 acc -> fp16, staged in smem (272B row stride, conflict-free)
    __syncthreads();
#pragma unroll
    for (int mt = 0; mt < 4; mt++) {
        const int r = wm * 64 + mt * 16 + g;
#pragma unroll
        for (int nt = 0; nt < 8; nt++) {
            const int col = wn * 64 + nt * 8 + qp * 2;
            *(half2*)(smem + r * 272 + col * 2) =
                __floats2half2_rn(acc[mt][nt][0], acc[mt][nt][1]);
            *(half2*)(smem + (r + 8) * 272 + col * 2) =
                __floats2half2_rn(acc[mt][nt][2], acc[mt][nt][3]);
        }
    }
    __syncthreads();
#pragma unroll
    for (int i = 0; i < 16; i++) {
        const int idx = t + i * 128;
        const int r = idx >> 4, colq = idx & 15;
        uint4 v = *(uint4*)(smem + r * 272 + colq * 16);
        *(uint4*)(g_Uhi + ((m0 + r) * 128 + o) * 512 + j0 + colq * 8) = v;
    }
}

// -------------------- stage 2: out = Uhi @ (in2_hi + in2_lo)^T + p + q + b ----
// grid (2, 256, 8): x = y-tile, y = x index, z = b
__global__ __launch_bounds__(128, 2) void stage2_mma(const float* __restrict__ w2,
                                                     float* __restrict__ out) {
    extern __shared__ char smem[];
    __shared__ float pb_s[128];
    const int t = threadIdx.x, lane = t & 31, wid = t >> 5;
    const int wm = wid & 1, wn = wid >> 1;
    const int g = lane >> 2, qp = lane & 3;

    const int b = blockIdx.z, x = blockIdx.y, n0 = blockIdx.x * 128;
    const size_t a_row0 = ((size_t)b * L_ + x) * 128;   // U rows (o)
    const size_t b_row0 = (size_t)b * L_ + n0;          // in2 rows (y)

    float acc[4][8][4];
#pragma unroll
    for (int i = 0; i < 4; i++)
#pragma unroll
        for (int j = 0; j < 8; j++)
#pragma unroll
            for (int k = 0; k < 4; k++) acc[i][j][k] = 0.f;

    mma_mainloop<false>(smem, g_Uhi + a_row0 * 512, g_I2hi + b_row0 * 512,
                        g_I2lo + b_row0 * 512, acc, wm, wn, lane, t);

    __syncthreads();
    if (t < 128) pb_s[t] = g_p[((size_t)b * L_ + x) * 128 + t] + w2[(size_t)1024 * 128 + t];
    __syncthreads();

    // stage S[y][o] fp32, row stride 132 floats (conflict-free writes, uint4 reads)
    float* S = (float*)smem;
#pragma unroll
    for (int mt = 0; mt < 4; mt++) {
        const int o = wm * 64 + mt * 16 + g;
        const float pb0 = pb_s[o], pb1 = pb_s[o + 8];
#pragma unroll
        for (int nt = 0; nt < 8; nt++) {
            const int y = wn * 64 + nt * 8 + qp * 2;
            S[y * 132 + o]           = acc[mt][nt][0] + pb0;
            S[(y + 1) * 132 + o]     = acc[mt][nt][1] + pb0;
            S[y * 132 + o + 8]       = acc[mt][nt][2] + pb1;
            S[(y + 1) * 132 + o + 8] = acc[mt][nt][3] + pb1;
        }
    }
    __syncthreads();
#pragma unroll
    for (int i = 0; i < 32; i++) {
        const int task = t + i * 128;
        const int y = task >> 5, oq = task & 31;
        const int yg = n0 + y;
        float4 v = *(float4*)&S[y * 132 + oq * 4];
        float4 qv = *(const float4*)&g_q[((size_t)b * L_ + yg) * 128 + oq * 4];
        v.x += qv.x; v.y += qv.y; v.z += qv.z; v.w += qv.w;
        *(float4*)(out + (((size_t)b * L_ + x) * L_ + yg) * 128 + oq * 4) = v;
    }
}

// -------------------- conversion kernels --------------------
__global__ __launch_bounds__(256) void split_kernel(const float* __restrict__ src, int which) {
    const int i = blockIdx.x * 256 + threadIdx.x;   // float4 index
    float4 v = ((const float4*)src)[i];
    hf h0 = __float2half_rn(v.x), h1 = __float2half_rn(v.y);
    hf h2 = __float2half_rn(v.z), h3 = __float2half_rn(v.w);
    half2 hi0 = __halves2half2(h0, h1), hi1 = __halves2half2(h2, h3);
    half2 lo0 = __halves2half2(__float2half_rn(v.x - __half2float(h0)),
                               __float2half_rn(v.y - __half2float(h1)));
    half2 lo1 = __halves2half2(__float2half_rn(v.z - __half2float(h2)),
                               __float2half_rn(v.w - __half2float(h3)));
    hf* dh = which ? g_I2hi : g_Ahi;
    hf* dl = which ? g_I2lo : g_Alo;
    ((half2*)dh)[2 * i] = hi0; ((half2*)dh)[2 * i + 1] = hi1;
    ((half2*)dl)[2 * i] = lo0; ((half2*)dl)[2 * i + 1] = lo1;
}

// w1 (512 x 65536) -> Whi[n][k] fp16 transposed
__global__ __launch_bounds__(256) void w1t_kernel(const float* __restrict__ w1) {
    __shared__ float sm[64][33];
    const int n0 = blockIdx.x * 32;
    const int k0 = blockIdx.y * 64;
    const int t = threadIdx.x;
#pragma unroll
    for (int it = 0; it < 8; it++) {
        const int idx = t + it * 256;
        const int i = idx >> 5, j = idx & 31;
        sm[i][j] = w1[(size_t)(k0 + i) * 65536 + n0 + j];
    }
    __syncthreads();
    const int n = t >> 3, kq = t & 7;
    hf h[8];
#pragma unroll
    for (int u = 0; u < 8; u++) h[u] = __float2half_rn(sm[kq * 8 + u][n]);
    *(uint4*)(g_Whi + (size_t)(n0 + n) * 512 + k0 + kq * 8) = *(uint4*)h;
}

// p[b,l,o] = sum_i in1[b,l,i]*w2a[i,o]; q likewise (fp32 exact)
__global__ __launch_bounds__(256) void pq_kernel(const float* __restrict__ in1,
                                                 const float* __restrict__ in2,
                                                 const float* __restrict__ w2) {
    const int o = threadIdx.x & 127;
    const int h = threadIdx.x >> 7;
    const int lt = blockIdx.x * 16;
    const int b = blockIdx.y;
    const int which = blockIdx.z;

    const float* inp = (which ? in2 : in1) + ((size_t)b * L_ + lt) * D_;
    const float* w = w2 + (size_t)which * D_ * O_;

    __shared__ float sin_[16][D_];
    for (int idx = threadIdx.x; idx < 16 * D_; idx += 256)
        sin_[idx / D_][idx % D_] = inp[idx];
    __syncthreads();

    float acc[8];
#pragma unroll
    for (int l = 0; l < 8; l++) acc[l] = 0.f;
    for (int i = 0; i < D_; i++) {
        const float wv = w[(size_t)i * O_ + o];
#pragma unroll
        for (int l = 0; l < 8; l++) acc[l] = fmaf(sin_[h * 8 + l][i], wv, acc[l]);
    }
    float* dst = (which ? g_q : g_p) + ((size_t)b * L_ + lt + h * 8) * O_;
#pragma unroll
    for (int l = 0; l < 8; l++) dst[(size_t)l * O_ + o] = acc[l];
}

// -------------------- host --------------------
extern "C" void kernel_launch(void* const* d_in, const int* in_sizes, int n_in,
                              void* d_out, int out_size) {
    const float* in1 = (const float*)d_in[0];
    const float* in2 = (const float*)d_in[1];
    const float* w1  = (const float*)d_in[2];
    const float* w2  = (const float*)d_in[3];
    float* out = (float*)d_out;

    cudaFuncSetAttribute(stage1_mma, cudaFuncAttributeMaxDynamicSharedMemorySize, SMEM_BYTES);
    cudaFuncSetAttribute(stage2_mma, cudaFuncAttributeMaxDynamicSharedMemorySize, SMEM_BYTES);

    split_kernel<<<2048 * 512 / 4 / 256, 256>>>(in1, 0);
    split_kernel<<<2048 * 512 / 4 / 256, 256>>>(in2, 1);
    w1t_kernel<<<dim3(65536 / 32, 512 / 64), 256>>>(w1);
    pq_kernel<<<dim3(L_ / 16, B_, 2), 256>>>(in1, in2, w2);

    stage1_mma<<<dim3(16, 512), 128, SMEM_BYTES>>>();
    stage2_mma<<<dim3(2, 256, 8), 128, SMEM_BYTES>>>(w2, out);
}

// round 5
// speedup vs baseline: 5.0805x; 1.5843x over previous
#include <cuda_runtime.h>
#include <cuda_fp16.h>
#include <cstdint>
#include <cstddef>

// Biaffine: out[b,x,y,o] = sum_ij in1[b,x,i] w1[i,o,j] in2[b,y,j] + p + q + bias
// Single fp16 GEMMs (precision budget: ~4-5e-4 < 1e-3):
//   stage1: U = in1_hi @ w1_hi^T      C(2048 x 65536), K=512
//   stage2: out = U_hi @ in2_hi^T     per (b,x): 128 x 256, K=512
// Rank-1 terms p,q,bias computed fp32-exact and fused in stage2 epilogue.
// Tensor path: mma.sync.aligned.m16n8k16.f32.f16.f16.f32 (plain sm_103 PTX).

#define B_ 8
#define L_ 256
#define D_ 512
#define O_ 128
#define NCH 16                  // 512 / 32
#define TBUF 10240              // 128 rows * 80B
#define CBUF (2 * TBUF)         // A + B tiles per chunk buffer
#define SMEM_BYTES 67584        // max(3*CBUF=61440, stage2 epi 128*132*4)

using hf = __half;

// -------------------- device globals (no runtime alloc) --------------------
__device__ __align__(128) hf g_Ahi[2048 * 512];
__device__ __align__(128) hf g_I2hi[2048 * 512];
__device__ __align__(128) hf g_Whi[(size_t)65536 * 512];
__device__ __align__(128) hf g_Uhi[(size_t)262144 * 512];
__device__ __align__(128) float g_p[2048 * 128];
__device__ __align__(128) float g_q[2048 * 128];

// -------------------- helpers --------------------
__device__ __forceinline__ uint32_t smem_u32(const void* p) {
    uint32_t a;
    asm("{ .reg .u64 t; cvta.to.shared.u64 t, %1; cvt.u32.u64 %0, t; }" : "=r"(a) : "l"(p));
    return a;
}
__device__ __forceinline__ void cpa16(uint32_t s, const void* g) {
    asm volatile("cp.async.cg.shared.global [%0], [%1], 16;" :: "r"(s), "l"(g));
}
#define CP_COMMIT asm volatile("cp.async.commit_group;" ::: "memory")
#define CP_WAIT1  asm volatile("cp.async.wait_group 1;" ::: "memory")
#define CP_WAIT0  asm volatile("cp.async.wait_group 0;" ::: "memory")

__device__ __forceinline__ void ldmx4(uint32_t* r, uint32_t addr) {
    asm volatile("ldmatrix.sync.aligned.m8n8.x4.shared.b16 {%0,%1,%2,%3}, [%4];"
                 : "=r"(r[0]), "=r"(r[1]), "=r"(r[2]), "=r"(r[3]) : "r"(addr));
}
__device__ __forceinline__ void mma16816(float* c, const uint32_t* a, uint32_t b0, uint32_t b1) {
    asm("mma.sync.aligned.m16n8k16.row.col.f32.f16.f16.f32 "
        "{%0,%1,%2,%3},{%4,%5,%6,%7},{%8,%9},{%0,%1,%2,%3};"
        : "+f"(c[0]), "+f"(c[1]), "+f"(c[2]), "+f"(c[3])
        : "r"(a[0]), "r"(a[1]), "r"(a[2]), "r"(a[3]), "r"(b0), "r"(b1));
}

// -------------------- chunk loader: A + B tiles 128x32 fp16 --------------------
__device__ __forceinline__ void load2(uint32_t sbase, int buf,
                                      const hf* __restrict__ ta,
                                      const hf* __restrict__ tb,
                                      int kcol, int t) {
    const int r = t >> 2, c = t & 3;
    const uint32_t so = sbase + buf * CBUF + r * 80 + c * 16;
    const size_t go = (size_t)r * 512 + kcol + c * 8;
    const hf* ga = ta + go;
    const hf* gb = tb + go;
#pragma unroll
    for (int p = 0; p < 4; p++) cpa16(so + p * (32 * 80), ga + (size_t)32 * p * 512);
#pragma unroll
    for (int p = 0; p < 4; p++) cpa16(so + TBUF + p * (32 * 80), gb + (size_t)32 * p * 512);
}

// -------------------- shared mainloop --------------------
// CTA tile 128x128, 4 warps in 2x2, warp tile 64x64.
// acc[mt][nt][4]: mt 0..3 (m16), nt 0..7 (n8).
__device__ __forceinline__ void mma_mainloop(char* smem,
                                             const hf* pa, const hf* pb,
                                             float acc[4][8][4],
                                             int wm, int wn, int lane, int t) {
    const uint32_t sbase = smem_u32(smem);
    const uint32_t lro = (lane & 15) * 80 + (lane >> 4) * 16;

    load2(sbase, 0, pa, pb, 0, t);  CP_COMMIT;
    load2(sbase, 1, pa, pb, 32, t); CP_COMMIT;

    for (int cch = 0; cch < NCH; cch++) {
        const int buf = cch % 3;
        if (cch < NCH - 1) { CP_WAIT1; } else { CP_WAIT0; }
        __syncthreads();

        const uint32_t sA = sbase + buf * CBUF + wm * (64 * 80) + lro;
        const uint32_t sB = sbase + buf * CBUF + TBUF + wn * (64 * 80) + lro;

#pragma unroll
        for (int kst = 0; kst < 2; kst++) {
            const uint32_t ko = kst * 32;
            uint32_t ar[4][4], br[4][4];
#pragma unroll
            for (int mt = 0; mt < 4; mt++) ldmx4(ar[mt], sA + mt * (16 * 80) + ko);
#pragma unroll
            for (int n2 = 0; n2 < 4; n2++) ldmx4(br[n2], sB + n2 * (16 * 80) + ko);
#pragma unroll
            for (int mt = 0; mt < 4; mt++)
#pragma unroll
                for (int n2 = 0; n2 < 4; n2++) {
                    mma16816(acc[mt][n2 * 2 + 0], ar[mt], br[n2][0], br[n2][2]);
                    mma16816(acc[mt][n2 * 2 + 1], ar[mt], br[n2][1], br[n2][3]);
                }
        }

        if (cch + 2 < NCH)
            { load2(sbase, (cch + 2) % 3, pa, pb, (cch + 2) * 32, t); CP_COMMIT; }
    }
}

// -------------------- stage 1: U = Ahi @ Whi^T --------------------
// grid (16, 512): x = m-tile (2048/128), y = n-tile (65536/128)
__global__ __launch_bounds__(128, 2) void stage1_mma() {
    extern __shared__ char smem[];
    const int t = threadIdx.x, lane = t & 31, wid = t >> 5;
    const int wm = wid & 1, wn = wid >> 1;
    const int g = lane >> 2, qp = lane & 3;

    const size_t m0 = (size_t)blockIdx.x * 128;
    const int n0 = blockIdx.y * 128;
    const int o = n0 >> 9, j0 = n0 & 511;

    float acc[4][8][4];
#pragma unroll
    for (int i = 0; i < 4; i++)
#pragma unroll
        for (int j = 0; j < 8; j++)
#pragma unroll
            for (int k = 0; k < 4; k++) acc[i][j][k] = 0.f;

    mma_mainloop(smem, g_Ahi + m0 * 512, g_Whi + (size_t)n0 * 512, acc, wm, wn, lane, t);

    // epilogue: fp32 acc -> fp16, staged in smem (272B row stride, conflict-free)
    __syncthreads();
#pragma unroll
    for (int mt = 0; mt < 4; mt++) {
        const int r = wm * 64 + mt * 16 + g;
#pragma unroll
        for (int nt = 0; nt < 8; nt++) {
            const int col = wn * 64 + nt * 8 + qp * 2;
            *(half2*)(smem + r * 272 + col * 2) =
                __floats2half2_rn(acc[mt][nt][0], acc[mt][nt][1]);
            *(half2*)(smem + (r + 8) * 272 + col * 2) =
                __floats2half2_rn(acc[mt][nt][2], acc[mt][nt][3]);
        }
    }
    __syncthreads();
#pragma unroll
    for (int i = 0; i < 16; i++) {
        const int idx = t + i * 128;
        const int r = idx >> 4, colq = idx & 15;
        uint4 v = *(uint4*)(smem + r * 272 + colq * 16);
        *(uint4*)(g_Uhi + ((m0 + r) * 128 + o) * 512 + j0 + colq * 8) = v;
    }
}

// -------------------- stage 2: out = Uhi @ I2hi^T + p + q + b ----
// grid (2, 256, 8): x = y-tile, y = x index, z = b
__global__ __launch_bounds__(128, 2) void stage2_mma(const float* __restrict__ w2,
                                                     float* __restrict__ out) {
    extern __shared__ char smem[];
    __shared__ float pb_s[128];
    const int t = threadIdx.x, lane = t & 31, wid = t >> 5;
    const int wm = wid & 1, wn = wid >> 1;
    const int g = lane >> 2, qp = lane & 3;

    const int b = blockIdx.z, x = blockIdx.y, n0 = blockIdx.x * 128;
    const size_t a_row0 = ((size_t)b * L_ + x) * 128;   // U rows (o)
    const size_t b_row0 = (size_t)b * L_ + n0;          // in2 rows (y)

    float acc[4][8][4];
#pragma unroll
    for (int i = 0; i < 4; i++)
#pragma unroll
        for (int j = 0; j < 8; j++)
#pragma unroll
            for (int k = 0; k < 4; k++) acc[i][j][k] = 0.f;

    mma_mainloop(smem, g_Uhi + a_row0 * 512, g_I2hi + b_row0 * 512, acc, wm, wn, lane, t);

    __syncthreads();
    if (t < 128) pb_s[t] = g_p[((size_t)b * L_ + x) * 128 + t] + w2[(size_t)1024 * 128 + t];
    __syncthreads();

    // stage S[y][o] fp32, row stride 132 floats (conflict-free writes, uint4 reads)
    float* S = (float*)smem;
#pragma unroll
    for (int mt = 0; mt < 4; mt++) {
        const int o = wm * 64 + mt * 16 + g;
        const float pb0 = pb_s[o], pb1 = pb_s[o + 8];
#pragma unroll
        for (int nt = 0; nt < 8; nt++) {
            const int y = wn * 64 + nt * 8 + qp * 2;
            S[y * 132 + o]           = acc[mt][nt][0] + pb0;
            S[(y + 1) * 132 + o]     = acc[mt][nt][1] + pb0;
            S[y * 132 + o + 8]       = acc[mt][nt][2] + pb1;
            S[(y + 1) * 132 + o + 8] = acc[mt][nt][3] + pb1;
        }
    }
    __syncthreads();
#pragma unroll
    for (int i = 0; i < 32; i++) {
        const int task = t + i * 128;
        const int y = task >> 5, oq = task & 31;
        const int yg = n0 + y;
        float4 v = *(float4*)&S[y * 132 + oq * 4];
        float4 qv = *(const float4*)&g_q[((size_t)b * L_ + yg) * 128 + oq * 4];
        v.x += qv.x; v.y += qv.y; v.z += qv.z; v.w += qv.w;
        *(float4*)(out + (((size_t)b * L_ + x) * L_ + yg) * 128 + oq * 4) = v;
    }
}

// -------------------- conversion kernels --------------------
__global__ __launch_bounds__(256) void cvt_kernel(const float* __restrict__ src, int which) {
    const int i = blockIdx.x * 256 + threadIdx.x;   // float4 index
    float4 v = ((const float4*)src)[i];
    half2 h0 = __floats2half2_rn(v.x, v.y);
    half2 h1 = __floats2half2_rn(v.z, v.w);
    hf* dh = which ? g_I2hi : g_Ahi;
    ((half2*)dh)[2 * i] = h0;
    ((half2*)dh)[2 * i + 1] = h1;
}

// w1 (512 x 65536) -> Whi[n][k] fp16 transposed
__global__ __launch_bounds__(256) void w1t_kernel(const float* __restrict__ w1) {
    __shared__ float sm[64][33];
    const int n0 = blockIdx.x * 32;
    const int k0 = blockIdx.y * 64;
    const int t = threadIdx.x;
#pragma unroll
    for (int it = 0; it < 8; it++) {
        const int idx = t + it * 256;
        const int i = idx >> 5, j = idx & 31;
        sm[i][j] = w1[(size_t)(k0 + i) * 65536 + n0 + j];
    }
    __syncthreads();
    const int n = t >> 3, kq = t & 7;
    hf h[8];
#pragma unroll
    for (int u = 0; u < 8; u++) h[u] = __float2half_rn(sm[kq * 8 + u][n]);
    *(uint4*)(g_Whi + (size_t)(n0 + n) * 512 + k0 + kq * 8) = *(uint4*)h;
}

// p[b,l,o] = sum_i in1[b,l,i]*w2a[i,o]; q likewise (fp32 exact)
__global__ __launch_bounds__(128) void pq_kernel(const float* __restrict__ in1,
                                                 const float* __restrict__ in2,
                                                 const float* __restrict__ w2) {
    const int o = threadIdx.x;
    const int lt = blockIdx.x * 16;
    const int b = blockIdx.y;
    const int which = blockIdx.z;

    const float* inp = (which ? in2 : in1) + ((size_t)b * L_ + lt) * D_;
    const float* w = w2 + (size_t)which * D_ * O_;

    __shared__ float sin_[16][D_];
    for (int idx = threadIdx.x; idx < 16 * D_; idx += 128)
        sin_[idx / D_][idx % D_] = inp[idx];
    __syncthreads();

    float acc[16];
#pragma unroll
    for (int l = 0; l < 16; l++) acc[l] = 0.f;
    for (int i = 0; i < D_; i++) {
        const float wv = w[(size_t)i * O_ + o];
#pragma unroll
        for (int l = 0; l < 16; l++) acc[l] = fmaf(sin_[l][i], wv, acc[l]);
    }
    float* dst = (which ? g_q : g_p) + ((size_t)b * L_ + lt) * O_;
#pragma unroll
    for (int l = 0; l < 16; l++) dst[(size_t)l * O_ + o] = acc[l];
}

// -------------------- host --------------------
extern "C" void kernel_launch(void* const* d_in, const int* in_sizes, int n_in,
                              void* d_out, int out_size) {
    const float* in1 = (const float*)d_in[0];
    const float* in2 = (const float*)d_in[1];
    const float* w1  = (const float*)d_in[2];
    const float* w2  = (const float*)d_in[3];
    float* out = (float*)d_out;

    cudaFuncSetAttribute(stage1_mma, cudaFuncAttributeMaxDynamicSharedMemorySize, SMEM_BYTES);
    cudaFuncSetAttribute(stage2_mma, cudaFuncAttributeMaxDynamicSharedMemorySize, SMEM_BYTES);

    cvt_kernel<<<2048 * 512 / 4 / 256, 256>>>(in1, 0);
    cvt_kernel<<<2048 * 512 / 4 / 256, 256>>>(in2, 1);
    w1t_kernel<<<dim3(65536 / 32, 512 / 64), 256>>>(w1);
    pq_kernel<<<dim3(L_ / 16, B_, 2), 128>>>(in1, in2, w2);

    stage1_mma<<<dim3(16, 512), 128, SMEM_BYTES>>>();
    stage2_mma<<<dim3(2, 256, 8), 128, SMEM_BYTES>>>(w2, out);
}